// round 14
// baseline (speedup 1.0000x reference)
#include <cuda_runtime.h>
#include <cuda_bf16.h>
#include <cstdint>

// Problem constants (fixed by the dataset)
#define BS 8
#define NQ 2048
#define MP 64
#define DD 1024

// Tiling
#define KC 64                  // K-chunk (d elems) per stage
#define NCHUNKS (DD / KC)      // 16
#define ASTRIDE 72             // row stride in bf16 elems (144 B)
#define NROWS 128              // CTA rows (N tile)
#define NTHREADS 384           // 8 consumer warps (4x2) + 4 producer warps
#define NSTAGES 3

// Smem (bytes): per stage [q][q2][B1][B2]
#define QBYTES   (NROWS * ASTRIDE * 2)      // 18432
#define BBYTES   (MP * ASTRIDE * 2)         // 9216
#define STAGEB   (2 * QBYTES + 2 * BBYTES)  // 55296
#define SMEM_TOTAL (NSTAGES * STAGEB)       // 165888
#define ROWB     (ASTRIDE * 2)              // 144 bytes per row

// __device__ scratch (allocation-free rule)
__device__ __nv_bfloat16 g_B1[BS * MP * DD];   // mask^2
__device__ __nv_bfloat16 g_B2[BS * MP * DD];   // -2 * mask^2 * p
__device__ float         g_pterm[BS * MP];     // sum_d (mask*p)^2

// ---------------------------------------------------------------------------
// Prep: vectorized + shfl reduction. grid = BS*MP = 512, block = 256.
// ---------------------------------------------------------------------------
__global__ __launch_bounds__(256, 4)
void proto_prep_kernel(const float* __restrict__ proto,
                       const float* __restrict__ mask) {
    const int bm   = blockIdx.x;
    const int t    = threadIdx.x;
    const int warp = t >> 5;
    const int lane = t & 31;

    float4 mk = ((const float4*)(mask  + (size_t)bm * DD))[t];
    float4 p  = ((const float4*)(proto + (size_t)bm * DD))[t];

    float4 m2 = make_float4(mk.x * mk.x, mk.y * mk.y, mk.z * mk.z, mk.w * mk.w);
    float4 b2 = make_float4(-2.f * m2.x * p.x, -2.f * m2.y * p.y,
                            -2.f * m2.z * p.z, -2.f * m2.w * p.w);

    __nv_bfloat162 a01 = __floats2bfloat162_rn(m2.x, m2.y);
    __nv_bfloat162 a23 = __floats2bfloat162_rn(m2.z, m2.w);
    __nv_bfloat162 c01 = __floats2bfloat162_rn(b2.x, b2.y);
    __nv_bfloat162 c23 = __floats2bfloat162_rn(b2.z, b2.w);
    uint2 u1 = make_uint2(*(uint32_t*)&a01, *(uint32_t*)&a23);
    uint2 u2 = make_uint2(*(uint32_t*)&c01, *(uint32_t*)&c23);
    *(uint2*)(g_B1 + (size_t)bm * DD + t * 4) = u1;
    *(uint2*)(g_B2 + (size_t)bm * DD + t * 4) = u2;

    float mpx = mk.x * p.x, mpy = mk.y * p.y, mpz = mk.z * p.z, mpw = mk.w * p.w;
    float psum = mpx * mpx + mpy * mpy + mpz * mpz + mpw * mpw;

    #pragma unroll
    for (int o = 16; o > 0; o >>= 1)
        psum += __shfl_xor_sync(0xffffffffu, psum, o);

    __shared__ float red[8];
    if (lane == 0) red[warp] = psum;
    __syncthreads();
    if (t < 8) {
        float v = red[t];
        v += __shfl_xor_sync(0xffu, v, 4);
        v += __shfl_xor_sync(0xffu, v, 2);
        v += __shfl_xor_sync(0xffu, v, 1);
        if (t == 0) g_pterm[bm] = v;
    }
}

// ---------------------------------------------------------------------------
// Helpers
// ---------------------------------------------------------------------------
__device__ __forceinline__ void cp_async16(void* smem_dst, const void* gmem_src) {
    uint32_t s = (uint32_t)__cvta_generic_to_shared(smem_dst);
    asm volatile("cp.async.cg.shared.global [%0], [%1], 16;\n" :: "r"(s), "l"(gmem_src));
}
__device__ __forceinline__ void ldsm_x4(uint32_t* r, uint32_t addr) {
    asm volatile("ldmatrix.sync.aligned.m8n8.x4.shared.b16 {%0,%1,%2,%3}, [%4];"
                 : "=r"(r[0]), "=r"(r[1]), "=r"(r[2]), "=r"(r[3]) : "r"(addr));
}
__device__ __forceinline__ void mbar_init(uint32_t a, uint32_t cnt) {
    asm volatile("mbarrier.init.shared.b64 [%0], %1;" :: "r"(a), "r"(cnt) : "memory");
}
__device__ __forceinline__ void mbar_arrive(uint32_t a) {
    asm volatile("mbarrier.arrive.shared.b64 _, [%0];" :: "r"(a) : "memory");
}
__device__ __forceinline__ void mbar_wait(uint32_t a, uint32_t ph) {
    asm volatile(
        "{\n\t.reg .pred P;\n\t"
        "LAB_%=:\n\t"
        "mbarrier.try_wait.parity.acquire.cta.shared::cta.b64 P, [%0], %1;\n\t"
        "@!P bra LAB_%=;\n\t}"
        :: "r"(a), "r"(ph) : "memory");
}

// ---------------------------------------------------------------------------
// Main kernel: warp-specialized fused dual-GEMM; producer precomputes q^2.
// grid = (16, 8) = 128 CTAs; 384 threads.
// Warps 0-7: consumers (4x2, warp tile 32x32, ldmatrix + mma.sync only).
// Warps 8-11: producers (q LDG->{q,q^2} bf16 STS, B cp.async), 3-stage ring.
// ---------------------------------------------------------------------------
__global__ __launch_bounds__(NTHREADS, 1)
void proto_logits_kernel(const float* __restrict__ q,
                         const float* __restrict__ scale,
                         float* __restrict__ out) {
    extern __shared__ __align__(16) char smem[];
    const uint32_t smem_u32 = (uint32_t)__cvta_generic_to_shared(smem);
    __shared__ __align__(8) unsigned long long s_mbar[2 * NSTAGES]; // [full0..2, empty0..2]
    const uint32_t mbar_u32 = (uint32_t)__cvta_generic_to_shared(s_mbar);

    const int b    = blockIdx.y;
    const int n0   = blockIdx.x * NROWS;
    const int t    = threadIdx.x;
    const int wid  = t >> 5;
    const int lane = t & 31;

    if (t == 0) {
        #pragma unroll
        for (int s = 0; s < NSTAGES; s++) {
            mbar_init(mbar_u32 + s * 8, 128);                  // full[s]: producers
            mbar_init(mbar_u32 + (NSTAGES + s) * 8, 256);      // empty[s]: consumers
        }
    }
    __syncthreads();

    const float*         qbase  = q    + ((size_t)b * NQ + n0) * DD;
    const __nv_bfloat16* B1base = g_B1 + (size_t)b * MP * DD;
    const __nv_bfloat16* B2base = g_B2 + (size_t)b * MP * DD;

    if (wid >= 8) {
        // ===================== PRODUCER (128 threads) =====================
        const int pt = t - 256;
        int s = 0, pe = 1;   // first pass through the ring is free
        for (int i = 0; i < NCHUNKS; ++i) {
            mbar_wait(mbar_u32 + (NSTAGES + s) * 8, pe);
            char* stage = smem + s * STAGEB;
            const int d0 = i * KC;

            // B cp.async (latency rides under q work)
            __nv_bfloat16* sB1 = (__nv_bfloat16*)(stage + 2 * QBYTES);
            #pragma unroll
            for (int h = 0; h < 8; h++) {
                int idx = pt + 128 * h;
                int mat = idx >> 9;
                int row = (idx >> 3) & 63;
                int g   = idx & 7;
                const __nv_bfloat16* src =
                    (mat ? B2base : B1base) + (size_t)row * DD + d0 + g * 8;
                cp_async16(sB1 + mat * (BBYTES / 2) + row * ASTRIDE + g * 8, src);
            }
            asm volatile("cp.async.commit_group;\n");

            // q: all 16 LDGs first (MLP=16), then cvt+STS of q and q^2
            __nv_bfloat16* sQ  = (__nv_bfloat16*)stage;
            __nv_bfloat16* sQ2 = (__nv_bfloat16*)(stage + QBYTES);
            float4 v[16];
            #pragma unroll
            for (int h = 0; h < 16; h++) {
                int gidx = pt + 128 * h;
                v[h] = *(const float4*)(qbase + (size_t)(gidx >> 4) * DD + d0 + (gidx & 15) * 4);
            }
            #pragma unroll
            for (int h = 0; h < 16; h++) {
                int gidx = pt + 128 * h;
                int so = (gidx >> 4) * ASTRIDE + (gidx & 15) * 4;
                __nv_bfloat162 lo = __floats2bfloat162_rn(v[h].x, v[h].y);
                __nv_bfloat162 hi = __floats2bfloat162_rn(v[h].z, v[h].w);
                uint2 w = make_uint2(*(uint32_t*)&lo, *(uint32_t*)&hi);
                *(uint2*)(&sQ[so]) = w;
                __nv_bfloat162 slo = __floats2bfloat162_rn(v[h].x * v[h].x, v[h].y * v[h].y);
                __nv_bfloat162 shi = __floats2bfloat162_rn(v[h].z * v[h].z, v[h].w * v[h].w);
                uint2 w2 = make_uint2(*(uint32_t*)&slo, *(uint32_t*)&shi);
                *(uint2*)(&sQ2[so]) = w2;
            }
            asm volatile("cp.async.wait_group 0;\n");
            mbar_arrive(mbar_u32 + s * 8);   // full[s] (release)

            if (++s == NSTAGES) { s = 0; pe ^= 1; }
        }
        return;
    }

    // ======================= CONSUMER (256 threads) =======================
    const int warp = wid;
    const int wm   = warp >> 1;     // 0..3 : 32-row group
    const int wn   = warp & 1;      // 0..1 : 32-col group
    const int gid  = lane >> 2;
    const int tig  = lane & 3;

    const int rowA = wm * 32 + (lane & 7) + ((lane >> 3) & 1) * 8;
    const uint32_t aOffBase = (uint32_t)(rowA * ROWB + (lane >> 4) * 16);
    const int rowB = wn * 32 + (lane & 7) + (lane >> 4) * 8;
    const uint32_t bOffBase = (uint32_t)(rowB * ROWB + ((lane >> 3) & 1) * 16);

    float acc[2][4][4];
    #pragma unroll
    for (int i = 0; i < 2; i++)
        #pragma unroll
        for (int j = 0; j < 4; j++)
            #pragma unroll
            for (int k = 0; k < 4; k++) acc[i][j][k] = 0.f;

    int s = 0, pf = 0;
    for (int i = 0; i < NCHUNKS; ++i) {
        mbar_wait(mbar_u32 + s * 8, pf);     // full[s] (acquire)

        const uint32_t stage_u32 = smem_u32 + s * STAGEB;
        const uint32_t aQ  = stage_u32 + aOffBase;
        const uint32_t aQ2 = aQ + QBYTES;
        const uint32_t aB1 = stage_u32 + 2 * QBYTES + bOffBase;
        const uint32_t aB2 = aB1 + BBYTES;

        #pragma unroll
        for (int kki = 0; kki < 4; kki++) {
            const uint32_t kb = kki * 32;       // bytes along k
            uint32_t aq[2][4], aq2[2][4];
            #pragma unroll
            for (int mt = 0; mt < 2; mt++) {
                ldsm_x4(aq[mt],  aQ  + mt * (16 * ROWB) + kb);
                ldsm_x4(aq2[mt], aQ2 + mt * (16 * ROWB) + kb);
            }
            uint32_t b1f[8], b2f[8];
            #pragma unroll
            for (int ntp = 0; ntp < 2; ntp++) {
                ldsm_x4(&b1f[ntp * 4], aB1 + ntp * (16 * ROWB) + kb);
                ldsm_x4(&b2f[ntp * 4], aB2 + ntp * (16 * ROWB) + kb);
            }
            #pragma unroll
            for (int mt = 0; mt < 2; mt++)
                #pragma unroll
                for (int nt = 0; nt < 4; nt++) {
                    asm volatile(
                        "mma.sync.aligned.m16n8k16.row.col.f32.bf16.bf16.f32 "
                        "{%0,%1,%2,%3}, {%4,%5,%6,%7}, {%8,%9}, {%0,%1,%2,%3};\n"
                        : "+f"(acc[mt][nt][0]), "+f"(acc[mt][nt][1]),
                          "+f"(acc[mt][nt][2]), "+f"(acc[mt][nt][3])
                        : "r"(aq2[mt][0]), "r"(aq2[mt][1]),
                          "r"(aq2[mt][2]), "r"(aq2[mt][3]),
                          "r"(b1f[nt * 2]), "r"(b1f[nt * 2 + 1]));
                    asm volatile(
                        "mma.sync.aligned.m16n8k16.row.col.f32.bf16.bf16.f32 "
                        "{%0,%1,%2,%3}, {%4,%5,%6,%7}, {%8,%9}, {%0,%1,%2,%3};\n"
                        : "+f"(acc[mt][nt][0]), "+f"(acc[mt][nt][1]),
                          "+f"(acc[mt][nt][2]), "+f"(acc[mt][nt][3])
                        : "r"(aq[mt][0]), "r"(aq[mt][1]),
                          "r"(aq[mt][2]), "r"(aq[mt][3]),
                          "r"(b2f[nt * 2]), "r"(b2f[nt * 2 + 1]));
                }
        }

        mbar_arrive(mbar_u32 + (NSTAGES + s) * 8);   // empty[s]
        if (++s == NSTAGES) { s = 0; pf ^= 1; }
    }

    // ---- epilogue: out = scale/D * (acc + pterm[col])
    const float sc = scale[0] * (1.0f / (float)DD);
    float* obase = out + ((size_t)b * NQ + n0) * MP;
    const float* pt = g_pterm + b * MP;
    #pragma unroll
    for (int mt = 0; mt < 2; mt++) {
        #pragma unroll
        for (int nt = 0; nt < 4; nt++) {
            int r0 = wm * 32 + mt * 16 + gid;
            int c0 = wn * 32 + nt * 8 + tig * 2;
            float p0 = pt[c0];
            float p1 = pt[c0 + 1];
            float2 o01 = make_float2(sc * (acc[mt][nt][0] + p0),
                                     sc * (acc[mt][nt][1] + p1));
            float2 o23 = make_float2(sc * (acc[mt][nt][2] + p0),
                                     sc * (acc[mt][nt][3] + p1));
            *(float2*)(obase + (size_t)r0 * MP + c0)       = o01;
            *(float2*)(obase + (size_t)(r0 + 8) * MP + c0) = o23;
        }
    }
}

// ---------------------------------------------------------------------------
// Launch. Inputs: 0=prototypes, 1=masktypes, 2=query, 3=support,
// 4=support_labels, 5=scale. Output: [8,2048,64] f32.
// ---------------------------------------------------------------------------
extern "C" void kernel_launch(void* const* d_in, const int* in_sizes, int n_in,
                              void* d_out, int out_size) {
    const float* proto = (const float*)d_in[0];
    const float* mask  = (const float*)d_in[1];
    const float* query = (const float*)d_in[2];
    const float* scale = (const float*)d_in[5];
    float* out = (float*)d_out;

    cudaFuncSetAttribute(proto_logits_kernel,
                         cudaFuncAttributeMaxDynamicSharedMemorySize, SMEM_TOTAL);

    proto_prep_kernel<<<BS * MP, 256>>>(proto, mask);
    dim3 grid(NQ / NROWS, BS);
    proto_logits_kernel<<<grid, NTHREADS, SMEM_TOTAL>>>(query, scale, out);
}

// round 15
// speedup vs baseline: 1.1091x; 1.1091x over previous
#include <cuda_runtime.h>
#include <cuda_bf16.h>
#include <cstdint>

// Problem constants (fixed by the dataset)
#define BS 8
#define NQ 2048
#define MP 64
#define DD 1024

// Tiling
#define KC 64                  // K-chunk (d elems) per stage
#define NCHUNKS (DD / KC)      // 16
#define ASTRIDE 72             // row stride in bf16 elems (144 B)
#define NROWS 128              // CTA rows (N tile)
#define NTHREADS 384           // 8 consumer warps (4x2) + 4 producer warps
#define NSTAGES 4

// Smem (bytes)
#define QBYTES   (NROWS * ASTRIDE * 2)      // 18432
#define BBYTES   (MP * ASTRIDE * 2)         // 9216
#define STAGEB   (QBYTES + 2 * BBYTES)      // 36864
#define SMEM_TOTAL (NSTAGES * STAGEB)       // 147456
#define ROWB     (ASTRIDE * 2)              // 144 bytes per row

// __device__ scratch (allocation-free rule)
__device__ __nv_bfloat16 g_B1[BS * MP * DD];   // mask^2
__device__ __nv_bfloat16 g_B2[BS * MP * DD];   // -2 * mask^2 * p
__device__ float         g_pterm[BS * MP];     // sum_d (mask*p)^2

// ---------------------------------------------------------------------------
// Prep: vectorized + shfl reduction. grid = BS*MP = 512, block = 256.
// ---------------------------------------------------------------------------
__global__ __launch_bounds__(256, 4)
void proto_prep_kernel(const float* __restrict__ proto,
                       const float* __restrict__ mask) {
    const int bm   = blockIdx.x;
    const int t    = threadIdx.x;
    const int warp = t >> 5;
    const int lane = t & 31;

    float4 mk = ((const float4*)(mask  + (size_t)bm * DD))[t];
    float4 p  = ((const float4*)(proto + (size_t)bm * DD))[t];

    float4 m2 = make_float4(mk.x * mk.x, mk.y * mk.y, mk.z * mk.z, mk.w * mk.w);
    float4 b2 = make_float4(-2.f * m2.x * p.x, -2.f * m2.y * p.y,
                            -2.f * m2.z * p.z, -2.f * m2.w * p.w);

    __nv_bfloat162 a01 = __floats2bfloat162_rn(m2.x, m2.y);
    __nv_bfloat162 a23 = __floats2bfloat162_rn(m2.z, m2.w);
    __nv_bfloat162 c01 = __floats2bfloat162_rn(b2.x, b2.y);
    __nv_bfloat162 c23 = __floats2bfloat162_rn(b2.z, b2.w);
    uint2 u1 = make_uint2(*(uint32_t*)&a01, *(uint32_t*)&a23);
    uint2 u2 = make_uint2(*(uint32_t*)&c01, *(uint32_t*)&c23);
    *(uint2*)(g_B1 + (size_t)bm * DD + t * 4) = u1;
    *(uint2*)(g_B2 + (size_t)bm * DD + t * 4) = u2;

    float mpx = mk.x * p.x, mpy = mk.y * p.y, mpz = mk.z * p.z, mpw = mk.w * p.w;
    float psum = mpx * mpx + mpy * mpy + mpz * mpz + mpw * mpw;

    #pragma unroll
    for (int o = 16; o > 0; o >>= 1)
        psum += __shfl_xor_sync(0xffffffffu, psum, o);

    __shared__ float red[8];
    if (lane == 0) red[warp] = psum;
    __syncthreads();
    if (t < 8) {
        float v = red[t];
        v += __shfl_xor_sync(0xffu, v, 4);
        v += __shfl_xor_sync(0xffu, v, 2);
        v += __shfl_xor_sync(0xffu, v, 1);
        if (t == 0) g_pterm[bm] = v;
    }
}

// ---------------------------------------------------------------------------
// Helpers
// ---------------------------------------------------------------------------
__device__ __forceinline__ void cp_async16(void* smem_dst, const void* gmem_src) {
    uint32_t s = (uint32_t)__cvta_generic_to_shared(smem_dst);
    asm volatile("cp.async.cg.shared.global [%0], [%1], 16;\n" :: "r"(s), "l"(gmem_src));
}
__device__ __forceinline__ uint32_t sq_bf16x2(uint32_t x) {
    __nv_bfloat162 v = *reinterpret_cast<__nv_bfloat162*>(&x);
    __nv_bfloat162 r = __hmul2(v, v);
    return *reinterpret_cast<uint32_t*>(&r);
}
__device__ __forceinline__ void ldsm_x4(uint32_t* r, uint32_t addr) {
    asm volatile("ldmatrix.sync.aligned.m8n8.x4.shared.b16 {%0,%1,%2,%3}, [%4];"
                 : "=r"(r[0]), "=r"(r[1]), "=r"(r[2]), "=r"(r[3]) : "r"(addr));
}
__device__ __forceinline__ void mbar_init(uint32_t a, uint32_t cnt) {
    asm volatile("mbarrier.init.shared.b64 [%0], %1;" :: "r"(a), "r"(cnt) : "memory");
}
__device__ __forceinline__ void mbar_arrive(uint32_t a) {
    asm volatile("mbarrier.arrive.shared.b64 _, [%0];" :: "r"(a) : "memory");
}
__device__ __forceinline__ void mbar_wait(uint32_t a, uint32_t ph) {
    asm volatile(
        "{\n\t.reg .pred P;\n\t"
        "LAB_%=:\n\t"
        "mbarrier.try_wait.parity.acquire.cta.shared::cta.b64 P, [%0], %1;\n\t"
        "@!P bra LAB_%=;\n\t}"
        :: "r"(a), "r"(ph) : "memory");
}

// ---------------------------------------------------------------------------
// Main kernel: warp-specialized fused dual-GEMM, de-serialized MMA streams.
// grid = (16, 8) = 128 CTAs; 384 threads.
// Warps 0-7: consumers (4x2, warp tile 32x32, ldmatrix + mma.sync).
// Warps 8-11: producers (q LDG->cvt->STS, B cp.async), 4-stage ring.
// ---------------------------------------------------------------------------
__global__ __launch_bounds__(NTHREADS, 1)
void proto_logits_kernel(const float* __restrict__ q,
                         const float* __restrict__ scale,
                         float* __restrict__ out) {
    extern __shared__ __align__(16) char smem[];
    const uint32_t smem_u32 = (uint32_t)__cvta_generic_to_shared(smem);
    __shared__ __align__(8) unsigned long long s_mbar[2 * NSTAGES]; // [full0..3, empty0..3]
    const uint32_t mbar_u32 = (uint32_t)__cvta_generic_to_shared(s_mbar);

    const int b    = blockIdx.y;
    const int n0   = blockIdx.x * NROWS;
    const int t    = threadIdx.x;
    const int wid  = t >> 5;
    const int lane = t & 31;

    if (t == 0) {
        #pragma unroll
        for (int s = 0; s < NSTAGES; s++) {
            mbar_init(mbar_u32 + s * 8, 128);                  // full[s]: producers
            mbar_init(mbar_u32 + (NSTAGES + s) * 8, 256);      // empty[s]: consumers
        }
    }
    __syncthreads();

    const float*         qbase  = q    + ((size_t)b * NQ + n0) * DD;
    const __nv_bfloat16* B1base = g_B1 + (size_t)b * MP * DD;
    const __nv_bfloat16* B2base = g_B2 + (size_t)b * MP * DD;

    if (wid >= 8) {
        // ===================== PRODUCER (128 threads) =====================
        const int pt = t - 256;
        int s = 0, pe = 1;   // first pass through the ring is free
        for (int i = 0; i < NCHUNKS; ++i) {
            mbar_wait(mbar_u32 + (NSTAGES + s) * 8, pe);
            char* stage = smem + s * STAGEB;
            const int d0 = i * KC;

            // B cp.async (latency rides under q work)
            __nv_bfloat16* sB1 = (__nv_bfloat16*)(stage + QBYTES);
            #pragma unroll
            for (int h = 0; h < 8; h++) {
                int idx = pt + 128 * h;
                int mat = idx >> 9;
                int row = (idx >> 3) & 63;
                int g   = idx & 7;
                const __nv_bfloat16* src =
                    (mat ? B2base : B1base) + (size_t)row * DD + d0 + g * 8;
                cp_async16(sB1 + mat * (BBYTES / 2) + row * ASTRIDE + g * 8, src);
            }
            asm volatile("cp.async.commit_group;\n");

            // q: issue ALL 16 LDGs first (MLP=16), then cvt+STS sweep
            __nv_bfloat16* sQ = (__nv_bfloat16*)stage;
            float4 v[16];
            #pragma unroll
            for (int h = 0; h < 16; h++) {
                int gidx = pt + 128 * h;
                v[h] = *(const float4*)(qbase + (size_t)(gidx >> 4) * DD + d0 + (gidx & 15) * 4);
            }
            #pragma unroll
            for (int h = 0; h < 16; h++) {
                int gidx = pt + 128 * h;
                int so = (gidx >> 4) * ASTRIDE + (gidx & 15) * 4;
                __nv_bfloat162 lo = __floats2bfloat162_rn(v[h].x, v[h].y);
                __nv_bfloat162 hi = __floats2bfloat162_rn(v[h].z, v[h].w);
                uint2 w = make_uint2(*(uint32_t*)&lo, *(uint32_t*)&hi);
                *(uint2*)(&sQ[so]) = w;
            }
            asm volatile("cp.async.wait_group 0;\n");
            mbar_arrive(mbar_u32 + s * 8);   // full[s] (release)

            if (++s == NSTAGES) { s = 0; pe ^= 1; }
        }
        return;
    }

    // ======================= CONSUMER (256 threads) =======================
    const int warp = wid;
    const int wm   = warp >> 1;     // 0..3 : 32-row group
    const int wn   = warp & 1;      // 0..1 : 32-col group
    const int gid  = lane >> 2;
    const int tig  = lane & 3;

    const int rowA = wm * 32 + (lane & 7) + ((lane >> 3) & 1) * 8;
    const uint32_t aOffBase = (uint32_t)(rowA * ROWB + (lane >> 4) * 16);
    const int rowB = wn * 32 + (lane & 7) + (lane >> 4) * 8;
    const uint32_t bOffBase = (uint32_t)(rowB * ROWB + ((lane >> 3) & 1) * 16);

    float acc[2][4][4];
    #pragma unroll
    for (int i = 0; i < 2; i++)
        #pragma unroll
        for (int j = 0; j < 4; j++)
            #pragma unroll
            for (int k = 0; k < 4; k++) acc[i][j][k] = 0.f;

    int s = 0, pf = 0;
    for (int i = 0; i < NCHUNKS; ++i) {
        mbar_wait(mbar_u32 + s * 8, pf);     // full[s] (acquire)

        const uint32_t stage_u32 = smem_u32 + s * STAGEB;
        const uint32_t aA  = stage_u32 + aOffBase;
        const uint32_t aB1 = stage_u32 + QBYTES + bOffBase;
        const uint32_t aB2 = aB1 + BBYTES;

        #pragma unroll
        for (int kki = 0; kki < 4; kki++) {
            const uint32_t kb = kki * 32;       // bytes along k
            uint32_t aq[2][4], aq2[2][4];
            #pragma unroll
            for (int mt = 0; mt < 2; mt++) {
                ldsm_x4(aq[mt], aA + mt * (16 * ROWB) + kb);
                #pragma unroll
                for (int r4 = 0; r4 < 4; r4++) aq2[mt][r4] = sq_bf16x2(aq[mt][r4]);
            }
            uint32_t b1f[8], b2f[8];
            #pragma unroll
            for (int ntp = 0; ntp < 2; ntp++) {
                ldsm_x4(&b1f[ntp * 4], aB1 + ntp * (16 * ROWB) + kb);
                ldsm_x4(&b2f[ntp * 4], aB2 + ntp * (16 * ROWB) + kb);
            }
            // Pass 1: 8 INDEPENDENT MMAs (distinct accumulators)
            #pragma unroll
            for (int mt = 0; mt < 2; mt++)
                #pragma unroll
                for (int nt = 0; nt < 4; nt++) {
                    asm volatile(
                        "mma.sync.aligned.m16n8k16.row.col.f32.bf16.bf16.f32 "
                        "{%0,%1,%2,%3}, {%4,%5,%6,%7}, {%8,%9}, {%0,%1,%2,%3};\n"
                        : "+f"(acc[mt][nt][0]), "+f"(acc[mt][nt][1]),
                          "+f"(acc[mt][nt][2]), "+f"(acc[mt][nt][3])
                        : "r"(aq2[mt][0]), "r"(aq2[mt][1]),
                          "r"(aq2[mt][2]), "r"(aq2[mt][3]),
                          "r"(b1f[nt * 2]), "r"(b1f[nt * 2 + 1]));
                }
            // Pass 2: dependency distance to pass 1 = 8 MMAs (fully covered)
            #pragma unroll
            for (int mt = 0; mt < 2; mt++)
                #pragma unroll
                for (int nt = 0; nt < 4; nt++) {
                    asm volatile(
                        "mma.sync.aligned.m16n8k16.row.col.f32.bf16.bf16.f32 "
                        "{%0,%1,%2,%3}, {%4,%5,%6,%7}, {%8,%9}, {%0,%1,%2,%3};\n"
                        : "+f"(acc[mt][nt][0]), "+f"(acc[mt][nt][1]),
                          "+f"(acc[mt][nt][2]), "+f"(acc[mt][nt][3])
                        : "r"(aq[mt][0]), "r"(aq[mt][1]),
                          "r"(aq[mt][2]), "r"(aq[mt][3]),
                          "r"(b2f[nt * 2]), "r"(b2f[nt * 2 + 1]));
                }
        }

        mbar_arrive(mbar_u32 + (NSTAGES + s) * 8);   // empty[s]
        if (++s == NSTAGES) { s = 0; pf ^= 1; }
    }

    // ---- epilogue: out = scale/D * (acc + pterm[col])
    const float sc = scale[0] * (1.0f / (float)DD);
    float* obase = out + ((size_t)b * NQ + n0) * MP;
    const float* pt = g_pterm + b * MP;
    #pragma unroll
    for (int mt = 0; mt < 2; mt++) {
        #pragma unroll
        for (int nt = 0; nt < 4; nt++) {
            int r0 = wm * 32 + mt * 16 + gid;
            int c0 = wn * 32 + nt * 8 + tig * 2;
            float p0 = pt[c0];
            float p1 = pt[c0 + 1];
            float2 o01 = make_float2(sc * (acc[mt][nt][0] + p0),
                                     sc * (acc[mt][nt][1] + p1));
            float2 o23 = make_float2(sc * (acc[mt][nt][2] + p0),
                                     sc * (acc[mt][nt][3] + p1));
            *(float2*)(obase + (size_t)r0 * MP + c0)       = o01;
            *(float2*)(obase + (size_t)(r0 + 8) * MP + c0) = o23;
        }
    }
}

// ---------------------------------------------------------------------------
// Launch. Inputs: 0=prototypes, 1=masktypes, 2=query, 3=support,
// 4=support_labels, 5=scale. Output: [8,2048,64] f32.
// ---------------------------------------------------------------------------
extern "C" void kernel_launch(void* const* d_in, const int* in_sizes, int n_in,
                              void* d_out, int out_size) {
    const float* proto = (const float*)d_in[0];
    const float* mask  = (const float*)d_in[1];
    const float* query = (const float*)d_in[2];
    const float* scale = (const float*)d_in[5];
    float* out = (float*)d_out;

    cudaFuncSetAttribute(proto_logits_kernel,
                         cudaFuncAttributeMaxDynamicSharedMemorySize, SMEM_TOTAL);

    proto_prep_kernel<<<BS * MP, 256>>>(proto, mask);
    dim3 grid(NQ / NROWS, BS);
    proto_logits_kernel<<<grid, NTHREADS, SMEM_TOTAL>>>(query, scale, out);
}